// round 3
// baseline (speedup 1.0000x reference)
#include <cuda_runtime.h>
#include <cuda_bf16.h>
#include <cstdint>

// Problem constants (fixed for MoELayer_20761871908984)
#define Bq     4
#define Sq     1024
#define Dq     1024
#define Hq     4096
#define Eq     8
#define Kq     2
#define NTOK   (Bq * Sq)        // 4096 tokens
#define MAXROW (NTOK * Kq)      // 8192 max (token, expert) rows

// -------- device-global scratch (no runtime allocation allowed) --------
__device__ int   g_counts[Eq];
__device__ int   g_lists[Eq][NTOK];
__device__ int   g_odd_nonzero;            // !=0 -> assign is int32; ==0 -> int64
__device__ float g_h[(size_t)MAXROW * Hq]; // 128 MB hidden activations (tf32-rounded)

// ---------------------------------------------------------------------
// Kernel 0: zero output + counters
// ---------------------------------------------------------------------
__global__ void k_zero(float* __restrict__ out, int n) {
    int i = blockIdx.x * blockDim.x + threadIdx.x;
    int stride = gridDim.x * blockDim.x;
    float4 z = make_float4(0.f, 0.f, 0.f, 0.f);
    int n4 = n >> 2;
    for (int j = i; j < n4; j += stride)
        reinterpret_cast<float4*>(out)[j] = z;
    for (int j = (n4 << 2) + i; j < n; j += stride)
        out[j] = 0.f;
    if (i == 0) {
        g_odd_nonzero = 0;
#pragma unroll
        for (int e = 0; e < Eq; e++) g_counts[e] = 0;
    }
}

// ---------------------------------------------------------------------
// Kernel 1: detect assign element width (int32 vs int64, little-endian)
// ---------------------------------------------------------------------
__global__ void k_detect(const int* __restrict__ a32) {
    int i = blockIdx.x * blockDim.x + threadIdx.x;   // [0, 4096)
    int idx = 2 * i + 1;
    if (idx < NTOK * Kq) {
        if (a32[idx] != 0) atomicOr(&g_odd_nonzero, 1);
    }
}

// ---------------------------------------------------------------------
// Kernel 2: build per-expert token lists (dedup within a token's K slots)
// ---------------------------------------------------------------------
__global__ void k_build(const int* __restrict__ a32) {
    int t = blockIdx.x * blockDim.x + threadIdx.x;
    if (t >= NTOK) return;
    int is64 = (g_odd_nonzero == 0);
    unsigned mask = 0;
#pragma unroll
    for (int j = 0; j < Kq; j++) {
        int e;
        if (is64) e = a32[(t * Kq + j) * 2];   // low word of int64
        else      e = a32[t * Kq + j];
        mask |= 1u << (e & (Eq - 1));
    }
    while (mask) {
        int e = __ffs(mask) - 1;
        mask &= mask - 1;
        int p = atomicAdd(&g_counts[e], 1);
        g_lists[e][p] = t;
    }
}

// ---------------------------------------------------------------------
// tf32 helpers
// ---------------------------------------------------------------------
__device__ __forceinline__ unsigned f2tf32(float f) {
    unsigned r;
    asm volatile("cvt.rna.tf32.f32 %0, %1;\n" : "=r"(r) : "f"(f));
    return r;
}
__device__ __forceinline__ float f2tf32f(float f) {
    return __uint_as_float(f2tf32(f));
}

__device__ __forceinline__ void mma_tf32(float& d0, float& d1, float& d2, float& d3,
                                         unsigned a0, unsigned a1, unsigned a2, unsigned a3,
                                         unsigned b0, unsigned b1) {
    asm volatile(
        "mma.sync.aligned.m16n8k8.row.col.f32.tf32.tf32.f32 "
        "{%0,%1,%2,%3},{%4,%5,%6,%7},{%8,%9},{%0,%1,%2,%3};\n"
        : "+f"(d0), "+f"(d1), "+f"(d2), "+f"(d3)
        : "r"(a0), "r"(a1), "r"(a2), "r"(a3), "r"(b0), "r"(b1));
}

#define ASTR 20    // A smem row stride (floats): 16 + 4 pad -> conflict-free STS + frag LDS.128
#define BSTR 136   // B smem row stride (floats): 128 + 8 pad -> conflict-free scalar frags

// ---------------------------------------------------------------------
// tf32 tensor-core grouped GEMM (mma.sync.m16n8k8)
//   CTA tile 128(M) x 128(N), BK=16, 256 threads, 8 warps of 64x32.
//   A staged via LDG.128 -> cvt.rna.tf32 -> STS with k-permutation
//   (k' = (k%4)*4 + k/4) so fragment loads are LDS.128.
//   B staged via LDG.128 -> cvt -> STS.128, natural [k][n] layout.
//   G1: A = gather(x), B = W1[e], out -> relu -> tf32-round -> g_h
//   G2: A = g_h rows (pre-rounded, no CVT), B = W2[e], out -> atomicAdd
// ---------------------------------------------------------------------
template<int KD, int ND, bool G1>
__global__ void __launch_bounds__(256, 2)
k_gemm_tc(const float* __restrict__ Ain,
          const float* __restrict__ W,
          const float* __restrict__ bias,
          float* __restrict__ out,
          const int* __restrict__ kp)
{
    const int e   = blockIdx.z;
    const int cnt = g_counts[e];
    const int m0  = blockIdx.y * 128;
    if (m0 >= cnt) return;
    const int n0  = blockIdx.x * 128;

    int base = 0;
#pragma unroll
    for (int i = 0; i < Eq; i++) base += (i < e) ? g_counts[i] : 0;

    __shared__ __align__(16) float As[2][128][ASTR];
    __shared__ __align__(16) float Bs[2][16][BSTR];
    __shared__ int toks[128];

    const int tid  = threadIdx.x;
    const int lane = tid & 31;
    const int wid  = tid >> 5;
    const int wm   = wid >> 2;     // 0..1  (64-row band)
    const int wn   = wid & 3;      // 0..3  (32-col band)
    const int g    = lane >> 2;    // 0..7
    const int c    = lane & 3;     // 0..3

    if (tid < 128) {
        int row = m0 + tid;
        toks[tid] = (row < cnt) ? g_lists[e][row] : 0;
    }
    __syncthreads();

    const float* Wp = W + (size_t)e * KD * ND;
    const int NK = KD / 16;

    // per-thread stage-load coordinates
    // A chunks: ch = tid + i*256 : m = ch>>2 (0..127), q = ch&3 (k quad)
    // B chunks: ch = tid + i*256 : k = ch>>5 (0..15),  nq = ch&31
    const int amA[2] = { tid >> 2, (tid + 256) >> 2 };
    const int aqA[2] = { tid & 3,  tid & 3 };
    const int bkB[2] = { tid >> 5, (tid + 256) >> 5 };
    const int bnB[2] = { tid & 31, tid & 31 };

    float4 rA[2], rB[2];

    auto ldg_stage = [&](int kt) {
#pragma unroll
        for (int i = 0; i < 2; i++) {
            int m = amA[i];
            int row = m0 + m;
            const float* src;
            if (G1) {
                src = Ain + (size_t)toks[m] * KD + kt * 16 + 4 * aqA[i];
            } else {
                size_t r = (row < cnt) ? (size_t)(base + row) : 0;
                src = g_h + r * KD + kt * 16 + 4 * aqA[i];
            }
            rA[i] = *reinterpret_cast<const float4*>(src);
        }
#pragma unroll
        for (int i = 0; i < 2; i++) {
            const float* src = Wp + (size_t)(kt * 16 + bkB[i]) * ND + n0 + 4 * bnB[i];
            rB[i] = *reinterpret_cast<const float4*>(src);
        }
    };

    auto sts_stage = [&](int buf) {
#pragma unroll
        for (int i = 0; i < 2; i++) {
            int m = amA[i], q = aqA[i];
            if (G1) {
                As[buf][m][q]      = f2tf32f(rA[i].x);
                As[buf][m][4 + q]  = f2tf32f(rA[i].y);
                As[buf][m][8 + q]  = f2tf32f(rA[i].z);
                As[buf][m][12 + q] = f2tf32f(rA[i].w);
            } else {
                As[buf][m][q]      = rA[i].x;   // g_h already tf32-rounded
                As[buf][m][4 + q]  = rA[i].y;
                As[buf][m][8 + q]  = rA[i].z;
                As[buf][m][12 + q] = rA[i].w;
            }
        }
#pragma unroll
        for (int i = 0; i < 2; i++) {
            float4 v;
            v.x = f2tf32f(rB[i].x);
            v.y = f2tf32f(rB[i].y);
            v.z = f2tf32f(rB[i].z);
            v.w = f2tf32f(rB[i].w);
            *reinterpret_cast<float4*>(&Bs[buf][bkB[i]][4 * bnB[i]]) = v;
        }
    };

    float acc[4][4][4];
#pragma unroll
    for (int i = 0; i < 4; i++)
#pragma unroll
        for (int j = 0; j < 4; j++)
#pragma unroll
            for (int r = 0; r < 4; r++) acc[i][j][r] = 0.f;

    ldg_stage(0);
    sts_stage(0);
    __syncthreads();

    for (int kt = 0; kt < NK; kt++) {
        const int buf = kt & 1;
        if (kt + 1 < NK) ldg_stage(kt + 1);

        // B fragments for both k8 steps: 16 scalar LDS (conflict-free)
        unsigned bf[2][4][2];
#pragma unroll
        for (int k8 = 0; k8 < 2; k8++) {
            const int kb = k8 * 8;
#pragma unroll
            for (int j = 0; j < 4; j++) {
                int nn = wn * 32 + j * 8 + g;
                bf[k8][j][0] = __float_as_uint(Bs[buf][kb + c][nn]);
                bf[k8][j][1] = __float_as_uint(Bs[buf][kb + c + 4][nn]);
            }
        }
        // A fragments: per i, two LDS.128 cover all 4 k-values (both k8)
#pragma unroll
        for (int i = 0; i < 4; i++) {
            int r0 = wm * 64 + i * 16 + g;
            float4 av0 = *reinterpret_cast<const float4*>(&As[buf][r0][c * 4]);
            float4 av1 = *reinterpret_cast<const float4*>(&As[buf][r0 + 8][c * 4]);
            // k8 = 0: k = c (x), c+4 (y)
#pragma unroll
            for (int j = 0; j < 4; j++)
                mma_tf32(acc[i][j][0], acc[i][j][1], acc[i][j][2], acc[i][j][3],
                         __float_as_uint(av0.x), __float_as_uint(av1.x),
                         __float_as_uint(av0.y), __float_as_uint(av1.y),
                         bf[0][j][0], bf[0][j][1]);
            // k8 = 1: k = c+8 (z), c+12 (w)
#pragma unroll
            for (int j = 0; j < 4; j++)
                mma_tf32(acc[i][j][0], acc[i][j][1], acc[i][j][2], acc[i][j][3],
                         __float_as_uint(av0.z), __float_as_uint(av1.z),
                         __float_as_uint(av0.w), __float_as_uint(av1.w),
                         bf[1][j][0], bf[1][j][1]);
        }
        __syncthreads();
        if (kt + 1 < NK) {
            sts_stage(buf ^ 1);
            __syncthreads();
        }
    }

    // ---- epilogue ----
    if (G1) {
        // relu(acc + b1) -> tf32-round -> g_h
#pragma unroll
        for (int j = 0; j < 4; j++) {
            int col = n0 + wn * 32 + j * 8 + 2 * c;
            float bv0 = __ldg(bias + (size_t)e * ND + col);
            float bv1 = __ldg(bias + (size_t)e * ND + col + 1);
#pragma unroll
            for (int i = 0; i < 4; i++) {
                int r0 = m0 + wm * 64 + i * 16 + g;
                if (r0 < cnt) {
                    float2 v;
                    v.x = f2tf32f(fmaxf(acc[i][j][0] + bv0, 0.f));
                    v.y = f2tf32f(fmaxf(acc[i][j][1] + bv1, 0.f));
                    *reinterpret_cast<float2*>(&g_h[(size_t)(base + r0) * ND + col]) = v;
                }
                int r1 = r0 + 8;
                if (r1 < cnt) {
                    float2 v;
                    v.x = f2tf32f(fmaxf(acc[i][j][2] + bv0, 0.f));
                    v.y = f2tf32f(fmaxf(acc[i][j][3] + bv1, 0.f));
                    *reinterpret_cast<float2*>(&g_h[(size_t)(base + r1) * ND + col]) = v;
                }
            }
        }
    } else {
        int kv = kp ? __ldg(kp) : Kq;
        if (kv <= 0) kv = Kq;
        float inv_k = 1.0f / (float)kv;
#pragma unroll
        for (int j = 0; j < 4; j++) {
            int col = n0 + wn * 32 + j * 8 + 2 * c;
            float bv0 = __ldg(bias + (size_t)e * ND + col);
            float bv1 = __ldg(bias + (size_t)e * ND + col + 1);
#pragma unroll
            for (int i = 0; i < 4; i++) {
                int r0 = m0 + wm * 64 + i * 16 + g;
                if (r0 < cnt) {
                    float* op = out + (size_t)toks[r0 - m0] * ND + col;
                    atomicAdd(op,     (acc[i][j][0] + bv0) * inv_k);
                    atomicAdd(op + 1, (acc[i][j][1] + bv1) * inv_k);
                }
                int r1 = r0 + 8;
                if (r1 < cnt) {
                    float* op = out + (size_t)toks[r1 - m0] * ND + col;
                    atomicAdd(op,     (acc[i][j][2] + bv0) * inv_k);
                    atomicAdd(op + 1, (acc[i][j][3] + bv1) * inv_k);
                }
            }
        }
    }
}

// ---------------------------------------------------------------------
// launch
// ---------------------------------------------------------------------
extern "C" void kernel_launch(void* const* d_in, const int* in_sizes, int n_in,
                              void* d_out, int out_size) {
    const float* x      = (const float*)d_in[0];
    const float* W1     = (const float*)d_in[1];
    const float* b1     = (const float*)d_in[2];
    const float* W2     = (const float*)d_in[3];
    const float* b2     = (const float*)d_in[4];
    const int*   assign = (const int*)d_in[5];
    const int*   kp     = (n_in >= 7) ? (const int*)d_in[6] : nullptr;
    float* out = (float*)d_out;

    k_zero<<<1024, 256>>>(out, out_size);
    k_detect<<<16, 256>>>(assign);
    k_build<<<16, 256>>>(assign);

    // GEMM1: [rows,1024] @ [1024,4096] -> relu -> g_h (tf32-rounded)
    dim3 g1(Hq / 128, NTOK / 128, Eq);
    k_gemm_tc<Dq, Hq, true><<<g1, 256>>>(x, W1, b1, nullptr, nullptr);

    // GEMM2: [rows,4096] @ [4096,1024] -> scatter-add out
    dim3 g2(Dq / 128, NTOK / 128, Eq);
    k_gemm_tc<Hq, Dq, false><<<g2, 256>>>(nullptr, W2, b2, out, kp);
}

// round 4
// speedup vs baseline: 1.1869x; 1.1869x over previous
#include <cuda_runtime.h>
#include <cuda_bf16.h>
#include <cstdint>

// Problem constants (fixed for MoELayer_20761871908984)
#define Bq     4
#define Sq     1024
#define Dq     1024
#define Hq     4096
#define Eq     8
#define Kq     2
#define NTOK   (Bq * Sq)        // 4096 tokens
#define MAXROW (NTOK * Kq)      // 8192 max (token, expert) rows

// -------- device-global scratch (no runtime allocation allowed) --------
__device__ int   g_counts[Eq];
__device__ int   g_lists[Eq][NTOK];
__device__ int   g_odd_nonzero;              // !=0 -> assign int32; ==0 -> int64
__device__ float g_h[(size_t)MAXROW * Hq];   // 128 MB hidden (tf32-rounded)
__device__ float g_xr[(size_t)NTOK * Dq];    // 16 MB  x  (tf32-rounded)
__device__ float g_w1r[(size_t)Eq * Dq * Hq];// 128 MB W1 (tf32-rounded)
__device__ float g_w2r[(size_t)Eq * Hq * Dq];// 128 MB W2 (tf32-rounded)

// ---------------------------------------------------------------------
__global__ void k_zero(float* __restrict__ out, int n) {
    int i = blockIdx.x * blockDim.x + threadIdx.x;
    int stride = gridDim.x * blockDim.x;
    float4 z = make_float4(0.f, 0.f, 0.f, 0.f);
    int n4 = n >> 2;
    for (int j = i; j < n4; j += stride)
        reinterpret_cast<float4*>(out)[j] = z;
    for (int j = (n4 << 2) + i; j < n; j += stride)
        out[j] = 0.f;
    if (i == 0) {
        g_odd_nonzero = 0;
#pragma unroll
        for (int e = 0; e < Eq; e++) g_counts[e] = 0;
    }
}

__global__ void k_detect(const int* __restrict__ a32) {
    int i = blockIdx.x * blockDim.x + threadIdx.x;   // [0, 4096)
    int idx = 2 * i + 1;
    if (idx < NTOK * Kq) {
        if (a32[idx] != 0) atomicOr(&g_odd_nonzero, 1);
    }
}

__global__ void k_build(const int* __restrict__ a32) {
    int t = blockIdx.x * blockDim.x + threadIdx.x;
    if (t >= NTOK) return;
    int is64 = (g_odd_nonzero == 0);
    unsigned mask = 0;
#pragma unroll
    for (int j = 0; j < Kq; j++) {
        int e;
        if (is64) e = a32[(t * Kq + j) * 2];
        else      e = a32[t * Kq + j];
        mask |= 1u << (e & (Eq - 1));
    }
    while (mask) {
        int e = __ffs(mask) - 1;
        mask &= mask - 1;
        int p = atomicAdd(&g_counts[e], 1);
        g_lists[e][p] = t;
    }
}

// ---------------------------------------------------------------------
// tf32 helpers
// ---------------------------------------------------------------------
__device__ __forceinline__ unsigned f2tf32(float f) {
    unsigned r;
    asm volatile("cvt.rna.tf32.f32 %0, %1;\n" : "=r"(r) : "f"(f));
    return r;
}
__device__ __forceinline__ float f2tf32f(float f) {
    return __uint_as_float(f2tf32(f));
}

// Prepass: dst = tf32_rna(src), vectorized
__global__ void k_round4(float* __restrict__ dst, const float* __restrict__ src, int n4) {
    int i = blockIdx.x * blockDim.x + threadIdx.x;
    int stride = gridDim.x * blockDim.x;
    for (; i < n4; i += stride) {
        float4 v = reinterpret_cast<const float4*>(src)[i];
        v.x = f2tf32f(v.x); v.y = f2tf32f(v.y);
        v.z = f2tf32f(v.z); v.w = f2tf32f(v.w);
        reinterpret_cast<float4*>(dst)[i] = v;
    }
}

__device__ __forceinline__ void mma_tf32(float& d0, float& d1, float& d2, float& d3,
                                         unsigned a0, unsigned a1, unsigned a2, unsigned a3,
                                         unsigned b0, unsigned b1) {
    asm volatile(
        "mma.sync.aligned.m16n8k8.row.col.f32.tf32.tf32.f32 "
        "{%0,%1,%2,%3},{%4,%5,%6,%7},{%8,%9},{%0,%1,%2,%3};\n"
        : "+f"(d0), "+f"(d1), "+f"(d2), "+f"(d3)
        : "r"(a0), "r"(a1), "r"(a2), "r"(a3), "r"(b0), "r"(b1));
}

__device__ __forceinline__ void ldsm_x4(unsigned& r0, unsigned& r1, unsigned& r2, unsigned& r3,
                                        uint32_t addr) {
    asm volatile("ldmatrix.sync.aligned.m8n8.x4.shared.b16 {%0,%1,%2,%3}, [%4];\n"
                 : "=r"(r0), "=r"(r1), "=r"(r2), "=r"(r3) : "r"(addr));
}

__device__ __forceinline__ void cp_async16(uint32_t smem_addr, const void* gptr) {
    asm volatile("cp.async.cg.shared.global [%0], [%1], 16;\n"
                 :: "r"(smem_addr), "l"(gptr));
}
__device__ __forceinline__ void cp_commit() { asm volatile("cp.async.commit_group;\n"); }
__device__ __forceinline__ void cp_wait1()  { asm volatile("cp.async.wait_group 1;\n"); }
__device__ __forceinline__ void cp_wait0()  { asm volatile("cp.async.wait_group 0;\n"); }

#define ASTR 20    // A smem row stride: 16 + 4 pad (16B-aligned rows, conflict-free LDSM)
#define BSTR 136   // B smem row stride: 128 + 8 pad (conflict-free scalar frags)
#define NSTG 3     // cp.async pipeline stages

// ---------------------------------------------------------------------
// tf32 grouped GEMM (mma.sync.m16n8k8), all operands pre-rounded to tf32.
// CTA tile 128x128, BK=16, 256 threads, 8 warps of 64x32.
// A frags: ldmatrix.x4.b16 on natural [m][k] layout. B frags: scalar LDS.
// 3-stage cp.async ring, 1 __syncthreads per stage.
// ---------------------------------------------------------------------
template<int KD, int ND, bool G1>
__global__ void __launch_bounds__(256, 2)
k_gemm_tc(const float* __restrict__ Ain,      // G1: g_xr ; G2: g_h
          const float* __restrict__ W,        // pre-rounded [E][KD][ND]
          const float* __restrict__ bias,
          float* __restrict__ out,
          const int* __restrict__ kp)
{
    const int e   = blockIdx.z;
    const int cnt = g_counts[e];
    const int m0  = blockIdx.y * 128;
    if (m0 >= cnt) return;
    const int n0  = blockIdx.x * 128;

    int base = 0;
#pragma unroll
    for (int i = 0; i < Eq; i++) base += (i < e) ? g_counts[i] : 0;

    __shared__ __align__(16) float As[NSTG][128][ASTR];
    __shared__ __align__(16) float Bs[NSTG][16][BSTR];
    __shared__ int toks[128];

    const int tid  = threadIdx.x;
    const int lane = tid & 31;
    const int wid  = tid >> 5;
    const int wm   = wid >> 2;     // 0..1
    const int wn   = wid & 3;      // 0..3
    const int g    = lane >> 2;    // 0..7
    const int c    = lane & 3;     // 0..3

    if (tid < 128) {
        int row = m0 + tid;
        toks[tid] = (row < cnt) ? g_lists[e][row] : 0;
    }
    __syncthreads();

    const float* Wp = W + (size_t)e * KD * ND;
    const int NK = KD / 16;

    // stage-load coordinates (2 A chunks + 2 B chunks per thread)
    const int amA[2] = { tid >> 2, (tid + 256) >> 2 };
    const int aqA    = tid & 3;
    const int bkB[2] = { tid >> 5, (tid + 256) >> 5 };
    const int bnB    = tid & 31;

    // A source row pointers (row 0 fallback for padding rows — values unused)
    const float* aSrc[2];
#pragma unroll
    for (int i = 0; i < 2; i++) {
        int m = amA[i];
        int row = m0 + m;
        if (G1) {
            aSrc[i] = Ain + (size_t)toks[m] * KD + 4 * aqA;
        } else {
            size_t r = (row < cnt) ? (size_t)(base + row) : 0;
            aSrc[i] = g_h + r * KD + 4 * aqA;
        }
    }

    auto load_stage = [&](int kt, int buf) {
        const int k0 = kt * 16;
#pragma unroll
        for (int i = 0; i < 2; i++) {
            uint32_t dst = (uint32_t)__cvta_generic_to_shared(&As[buf][amA[i]][4 * aqA]);
            cp_async16(dst, aSrc[i] + k0);
        }
#pragma unroll
        for (int i = 0; i < 2; i++) {
            const float* src = Wp + (size_t)(k0 + bkB[i]) * ND + n0 + 4 * bnB;
            uint32_t dst = (uint32_t)__cvta_generic_to_shared(&Bs[buf][bkB[i]][4 * bnB]);
            cp_async16(dst, src);
        }
        cp_commit();
    };

    float acc[4][4][4];
#pragma unroll
    for (int i = 0; i < 4; i++)
#pragma unroll
        for (int j = 0; j < 4; j++)
#pragma unroll
            for (int r = 0; r < 4; r++) acc[i][j][r] = 0.f;

    load_stage(0, 0);
    load_stage(1, 1);

    // ldmatrix lane address components (row/col within A tile)
    const int lrow = wm * 64 + (lane & 15);      // + i*16
    const int lcol = (lane >> 4) * 4;            // + k8*8

    for (int kt = 0; kt < NK; kt++) {
        const int buf = kt % NSTG;
        if (kt + 1 < NK) cp_wait1(); else cp_wait0();
        __syncthreads();
        if (kt + 2 < NK) load_stage(kt + 2, (kt + 2) % NSTG);

        // B fragments: 16 conflict-free scalar LDS
        unsigned bf[2][4][2];
#pragma unroll
        for (int k8 = 0; k8 < 2; k8++) {
            const int kb = k8 * 8;
#pragma unroll
            for (int j = 0; j < 4; j++) {
                int nn = wn * 32 + j * 8 + g;
                bf[k8][j][0] = __float_as_uint(Bs[buf][kb + c][nn]);
                bf[k8][j][1] = __float_as_uint(Bs[buf][kb + c + 4][nn]);
            }
        }
        // A fragments + MMA
#pragma unroll
        for (int i = 0; i < 4; i++) {
            uint32_t abase = (uint32_t)__cvta_generic_to_shared(
                &As[buf][lrow + i * 16][lcol]);
            unsigned a0, a1, a2, a3;
            ldsm_x4(a0, a1, a2, a3, abase);           // k 0..7
#pragma unroll
            for (int j = 0; j < 4; j++)
                mma_tf32(acc[i][j][0], acc[i][j][1], acc[i][j][2], acc[i][j][3],
                         a0, a1, a2, a3, bf[0][j][0], bf[0][j][1]);
            unsigned a4, a5, a6, a7;
            ldsm_x4(a4, a5, a6, a7, abase + 8 * 4);   // k 8..15
#pragma unroll
            for (int j = 0; j < 4; j++)
                mma_tf32(acc[i][j][0], acc[i][j][1], acc[i][j][2], acc[i][j][3],
                         a4, a5, a6, a7, bf[1][j][0], bf[1][j][1]);
        }
    }

    // ---- epilogue ----
    if (G1) {
#pragma unroll
        for (int j = 0; j < 4; j++) {
            int col = n0 + wn * 32 + j * 8 + 2 * c;
            float bv0 = __ldg(bias + (size_t)e * ND + col);
            float bv1 = __ldg(bias + (size_t)e * ND + col + 1);
#pragma unroll
            for (int i = 0; i < 4; i++) {
                int r0 = m0 + wm * 64 + i * 16 + g;
                if (r0 < cnt) {
                    float2 v;
                    v.x = f2tf32f(fmaxf(acc[i][j][0] + bv0, 0.f));
                    v.y = f2tf32f(fmaxf(acc[i][j][1] + bv1, 0.f));
                    *reinterpret_cast<float2*>(&g_h[(size_t)(base + r0) * ND + col]) = v;
                }
                int r1 = r0 + 8;
                if (r1 < cnt) {
                    float2 v;
                    v.x = f2tf32f(fmaxf(acc[i][j][2] + bv0, 0.f));
                    v.y = f2tf32f(fmaxf(acc[i][j][3] + bv1, 0.f));
                    *reinterpret_cast<float2*>(&g_h[(size_t)(base + r1) * ND + col]) = v;
                }
            }
        }
    } else {
        int kv = kp ? __ldg(kp) : Kq;
        if (kv <= 0) kv = Kq;
        float inv_k = 1.0f / (float)kv;
#pragma unroll
        for (int j = 0; j < 4; j++) {
            int col = n0 + wn * 32 + j * 8 + 2 * c;
            float bv0 = __ldg(bias + (size_t)e * ND + col);
            float bv1 = __ldg(bias + (size_t)e * ND + col + 1);
#pragma unroll
            for (int i = 0; i < 4; i++) {
                int r0 = m0 + wm * 64 + i * 16 + g;
                if (r0 < cnt) {
                    float* op = out + (size_t)toks[r0 - m0] * ND + col;
                    atomicAdd(op,     (acc[i][j][0] + bv0) * inv_k);
                    atomicAdd(op + 1, (acc[i][j][1] + bv1) * inv_k);
                }
                int r1 = r0 + 8;
                if (r1 < cnt) {
                    float* op = out + (size_t)toks[r1 - m0] * ND + col;
                    atomicAdd(op,     (acc[i][j][2] + bv0) * inv_k);
                    atomicAdd(op + 1, (acc[i][j][3] + bv1) * inv_k);
                }
            }
        }
    }
}

// ---------------------------------------------------------------------
// launch
// ---------------------------------------------------------------------
extern "C" void kernel_launch(void* const* d_in, const int* in_sizes, int n_in,
                              void* d_out, int out_size) {
    const float* x      = (const float*)d_in[0];
    const float* W1     = (const float*)d_in[1];
    const float* b1     = (const float*)d_in[2];
    const float* W2     = (const float*)d_in[3];
    const float* b2     = (const float*)d_in[4];
    const int*   assign = (const int*)d_in[5];
    const int*   kp     = (n_in >= 7) ? (const int*)d_in[6] : nullptr;
    float* out = (float*)d_out;

    k_zero<<<1024, 256>>>(out, out_size);
    k_detect<<<16, 256>>>(assign);
    k_build<<<16, 256>>>(assign);

    // prepass: tf32-round x, W1, W2 (RNA) into device buffers
    float* xr;  cudaGetSymbolAddress((void**)&xr,  g_xr);
    float* w1r; cudaGetSymbolAddress((void**)&w1r, g_w1r);
    float* w2r; cudaGetSymbolAddress((void**)&w2r, g_w2r);
    k_round4<<<1024, 256>>>(xr,  x,  NTOK * Dq / 4);
    k_round4<<<2048, 256>>>(w1r, W1, Eq * Dq * Hq / 4);
    k_round4<<<2048, 256>>>(w2r, W2, Eq * Hq * Dq / 4);

    // GEMM1: [rows,1024] @ [1024,4096] -> relu -> g_h (tf32-rounded)
    dim3 g1(Hq / 128, NTOK / 128, Eq);
    k_gemm_tc<Dq, Hq, true><<<g1, 256>>>(xr, w1r, b1, nullptr, nullptr);

    // GEMM2: [rows,4096] @ [4096,1024] -> scatter-add out
    dim3 g2(Dq / 128, NTOK / 128, Eq);
    k_gemm_tc<Hq, Dq, false><<<g2, 256>>>(nullptr, w2r, b2, out, kp);
}

// round 6
// speedup vs baseline: 1.3234x; 1.1151x over previous
#include <cuda_runtime.h>
#include <cuda_bf16.h>
#include <cstdint>

// Problem constants (fixed for MoELayer_20761871908984)
#define Bq     4
#define Sq     1024
#define Dq     1024
#define Hq     4096
#define Eq     8
#define Kq     2
#define NTOK   (Bq * Sq)        // 4096 tokens
#define MAXROW (NTOK * Kq)      // 8192 max (token, expert) rows

// -------- device-global scratch (no runtime allocation allowed) --------
__device__ int   g_counts[Eq];
__device__ int   g_lists[Eq][NTOK];
__device__ int   g_odd_nonzero;              // !=0 -> assign int32; ==0 -> int64
__device__ float g_h[(size_t)MAXROW * Hq];   // 128 MB hidden (tf32-rounded)
__device__ float g_xr[(size_t)NTOK * Dq];    // 16 MB  x  (tf32-rounded)
__device__ float g_w1r[(size_t)Eq * Dq * Hq];// 128 MB W1 (tf32-rounded)
__device__ float g_w2r[(size_t)Eq * Hq * Dq];// 128 MB W2 (tf32-rounded)

// ---------------------------------------------------------------------
__global__ void k_zero(float* __restrict__ out, int n) {
    int i = blockIdx.x * blockDim.x + threadIdx.x;
    int stride = gridDim.x * blockDim.x;
    float4 z = make_float4(0.f, 0.f, 0.f, 0.f);
    int n4 = n >> 2;
    for (int j = i; j < n4; j += stride)
        reinterpret_cast<float4*>(out)[j] = z;
    for (int j = (n4 << 2) + i; j < n; j += stride)
        out[j] = 0.f;
    if (i == 0) {
        g_odd_nonzero = 0;
#pragma unroll
        for (int e = 0; e < Eq; e++) g_counts[e] = 0;
    }
}

__global__ void k_detect(const int* __restrict__ a32) {
    int i = blockIdx.x * blockDim.x + threadIdx.x;   // [0, 4096)
    int idx = 2 * i + 1;
    if (idx < NTOK * Kq) {
        if (a32[idx] != 0) atomicOr(&g_odd_nonzero, 1);
    }
}

__global__ void k_build(const int* __restrict__ a32) {
    int t = blockIdx.x * blockDim.x + threadIdx.x;
    if (t >= NTOK) return;
    int is64 = (g_odd_nonzero == 0);
    unsigned mask = 0;
#pragma unroll
    for (int j = 0; j < Kq; j++) {
        int e;
        if (is64) e = a32[(t * Kq + j) * 2];
        else      e = a32[t * Kq + j];
        mask |= 1u << (e & (Eq - 1));
    }
    while (mask) {
        int e = __ffs(mask) - 1;
        mask &= mask - 1;
        int p = atomicAdd(&g_counts[e], 1);
        g_lists[e][p] = t;
    }
}

// ---------------------------------------------------------------------
// tf32 helpers
// ---------------------------------------------------------------------
__device__ __forceinline__ unsigned f2tf32(float f) {
    unsigned r;
    asm volatile("cvt.rna.tf32.f32 %0, %1;\n" : "=r"(r) : "f"(f));
    return r;
}
__device__ __forceinline__ float f2tf32f(float f) {
    return __uint_as_float(f2tf32(f));
}

// Prepass: dst = tf32_rna(src), vectorized grid-stride
__global__ void k_round4(float* __restrict__ dst, const float* __restrict__ src, int n4) {
    int i = blockIdx.x * blockDim.x + threadIdx.x;
    int stride = gridDim.x * blockDim.x;
    for (; i < n4; i += stride) {
        float4 v = reinterpret_cast<const float4*>(src)[i];
        v.x = f2tf32f(v.x); v.y = f2tf32f(v.y);
        v.z = f2tf32f(v.z); v.w = f2tf32f(v.w);
        reinterpret_cast<float4*>(dst)[i] = v;
    }
}

__device__ __forceinline__ void mma_tf32(float& d0, float& d1, float& d2, float& d3,
                                         unsigned a0, unsigned a1, unsigned a2, unsigned a3,
                                         unsigned b0, unsigned b1) {
    asm volatile(
        "mma.sync.aligned.m16n8k8.row.col.f32.tf32.tf32.f32 "
        "{%0,%1,%2,%3},{%4,%5,%6,%7},{%8,%9},{%0,%1,%2,%3};\n"
        : "+f"(d0), "+f"(d1), "+f"(d2), "+f"(d3)
        : "r"(a0), "r"(a1), "r"(a2), "r"(a3), "r"(b0), "r"(b1));
}

__device__ __forceinline__ void ldsm_x4(unsigned& r0, unsigned& r1, unsigned& r2, unsigned& r3,
                                        uint32_t addr) {
    asm volatile("ldmatrix.sync.aligned.m8n8.x4.shared.b16 {%0,%1,%2,%3}, [%4];\n"
                 : "=r"(r0), "=r"(r1), "=r"(r2), "=r"(r3) : "r"(addr));
}

__device__ __forceinline__ void cp_async16(uint32_t smem_addr, const void* gptr) {
    asm volatile("cp.async.cg.shared.global [%0], [%1], 16;\n"
                 :: "r"(smem_addr), "l"(gptr));
}
__device__ __forceinline__ void cp_commit() { asm volatile("cp.async.commit_group;\n"); }
__device__ __forceinline__ void cp_wait1()  { asm volatile("cp.async.wait_group 1;\n"); }
__device__ __forceinline__ void cp_wait0()  { asm volatile("cp.async.wait_group 0;\n"); }

// ---------------------------------------------------------------------
// Smem geometry (dynamic):  BK=32 per stage, 3 stages.
// A: [128][ASTR] floats, ASTR=36 (32 + 4 pad) -> conflict-free LDSM phases.
// B: [32][BSTR]  floats, BSTR=136 (128 + 8 pad) -> conflict-free scalar frags.
// ---------------------------------------------------------------------
#define ASTR 36
#define BSTR 136
#define NSTG 3
#define A_TILE_FLT (128 * ASTR)            // 4608 floats = 18432 B
#define B_TILE_FLT (32 * BSTR)             // 4352 floats = 17408 B
#define OFF_TOKS   0                       // 128 ints
#define OFF_A      512
#define OFF_B      (OFF_A + NSTG * A_TILE_FLT * 4)   // 512 + 55296
#define SMEM_TOTAL (OFF_B + NSTG * B_TILE_FLT * 4)   // ~108 KB

// ---------------------------------------------------------------------
// tf32 grouped GEMM (mma.sync.m16n8k8), operands pre-rounded to tf32.
// CTA tile 128x128, BK=32 per pipeline stage, 256 threads, 8 warps 64x32.
// ---------------------------------------------------------------------
template<int KD, int ND, bool G1>
__global__ void __launch_bounds__(256, 2)
k_gemm_tc(const float* __restrict__ Ain,      // G1: g_xr ; G2: g_h
          const float* __restrict__ W,        // pre-rounded [E][KD][ND]
          const float* __restrict__ bias,
          float* __restrict__ out,
          const int* __restrict__ kp)
{
    constexpr int NK = KD / 32;
    const int e   = blockIdx.z;
    const int cnt = g_counts[e];
    const int m0  = blockIdx.y * 128;
    if (m0 >= cnt) return;
    const int n0  = blockIdx.x * 128;

    int base = 0;
#pragma unroll
    for (int i = 0; i < Eq; i++) base += (i < e) ? g_counts[i] : 0;

    extern __shared__ __align__(16) char smem[];
    int*   toks = reinterpret_cast<int*>(smem + OFF_TOKS);
    float* As   = reinterpret_cast<float*>(smem + OFF_A);
    float* Bs   = reinterpret_cast<float*>(smem + OFF_B);

    const int tid  = threadIdx.x;
    const int lane = tid & 31;
    const int wid  = tid >> 5;
    const int wm   = wid >> 2;     // 0..1
    const int wn   = wid & 3;      // 0..3
    const int g    = lane >> 2;    // 0..7
    const int c    = lane & 3;     // 0..3

    if (tid < 128) {
        int row = m0 + tid;
        toks[tid] = (row < cnt) ? g_lists[e][row] : 0;
    }
    __syncthreads();

    const float* Wp = W + (size_t)e * KD * ND;

    // ---- stage-load coordinates ----
    // A: 1024 16B-chunks/stage -> 4 per thread. chunk ch: m = ch>>3, aq = ch&7.
    const int aq = tid & 7;
    const float* aSrc[4];
    uint32_t aDst[4];
#pragma unroll
    for (int i = 0; i < 4; i++) {
        int m = (tid >> 3) + 32 * i;
        int row = m0 + m;
        if (G1) aSrc[i] = Ain + (size_t)toks[m] * KD + 4 * aq;
        else    aSrc[i] = g_h + (size_t)((row < cnt) ? base + row : base) * KD + 4 * aq;
        aDst[i] = (uint32_t)((m * ASTR + 4 * aq) * 4);
    }
    // B: 1024 16B-chunks/stage -> 4 per thread. chunk ch: k = ch>>5, nq = ch&31.
    const int bnq = tid & 31;
    const int bk0 = tid >> 5;     // +8*i
    const uint32_t sbA = (uint32_t)__cvta_generic_to_shared(As);
    const uint32_t sbB = (uint32_t)__cvta_generic_to_shared(Bs);

    auto load_stage = [&](int kt, int buf) {
        const int k0 = kt * 32;
        const uint32_t dA = sbA + buf * A_TILE_FLT * 4;
        const uint32_t dB = sbB + buf * B_TILE_FLT * 4;
#pragma unroll
        for (int i = 0; i < 4; i++)
            cp_async16(dA + aDst[i], aSrc[i] + k0);
#pragma unroll
        for (int i = 0; i < 4; i++) {
            int k = bk0 + 8 * i;
            cp_async16(dB + (uint32_t)((k * BSTR + 4 * bnq) * 4),
                       Wp + (size_t)(k0 + k) * ND + n0 + 4 * bnq);
        }
        cp_commit();
    };

    float acc[4][4][4];
#pragma unroll
    for (int i = 0; i < 4; i++)
#pragma unroll
        for (int j = 0; j < 4; j++)
#pragma unroll
            for (int r = 0; r < 4; r++) acc[i][j][r] = 0.f;

    load_stage(0, 0);
    load_stage(1, 1);

    // ldmatrix lane addressing (row within A tile, 16B col segment)
    const int lrow = wm * 64 + (lane & 15);
    const int lcol = (lane >> 4) * 4;

    for (int kt = 0; kt < NK; kt++) {
        const int buf = kt % NSTG;
        if (kt + 1 < NK) cp_wait1(); else cp_wait0();
        __syncthreads();
        if (kt + 2 < NK) load_stage(kt + 2, (kt + 2) % NSTG);

        const float* Ab = As + buf * A_TILE_FLT;
        const float* Bb = Bs + buf * B_TILE_FLT;

#pragma unroll
        for (int h = 0; h < 2; h++) {          // two 16-k halves of BK=32
            const int kh = h * 16;
            // B fragments: 16 conflict-free scalar LDS
            unsigned bf[2][4][2];
#pragma unroll
            for (int k8 = 0; k8 < 2; k8++) {
                const int kb = kh + k8 * 8;
#pragma unroll
                for (int j = 0; j < 4; j++) {
                    int nn = wn * 32 + j * 8 + g;
                    bf[k8][j][0] = __float_as_uint(Bb[(kb + c) * BSTR + nn]);
                    bf[k8][j][1] = __float_as_uint(Bb[(kb + c + 4) * BSTR + nn]);
                }
            }
            // A fragments + MMA
#pragma unroll
            for (int i = 0; i < 4; i++) {
                uint32_t abase = (uint32_t)__cvta_generic_to_shared(
                    Ab + (lrow + i * 16) * ASTR + lcol + kh);
                unsigned a0, a1, a2, a3;
                ldsm_x4(a0, a1, a2, a3, abase);          // k kh..kh+7
#pragma unroll
                for (int j = 0; j < 4; j++)
                    mma_tf32(acc[i][j][0], acc[i][j][1], acc[i][j][2], acc[i][j][3],
                             a0, a1, a2, a3, bf[0][j][0], bf[0][j][1]);
                unsigned a4, a5, a6, a7;
                ldsm_x4(a4, a5, a6, a7, abase + 32);     // k kh+8..kh+15
#pragma unroll
                for (int j = 0; j < 4; j++)
                    mma_tf32(acc[i][j][0], acc[i][j][1], acc[i][j][2], acc[i][j][3],
                             a4, a5, a6, a7, bf[1][j][0], bf[1][j][1]);
            }
        }
    }

    // ---- epilogue ----
    if (G1) {
#pragma unroll
        for (int j = 0; j < 4; j++) {
            int col = n0 + wn * 32 + j * 8 + 2 * c;
            float bv0 = __ldg(bias + (size_t)e * ND + col);
            float bv1 = __ldg(bias + (size_t)e * ND + col + 1);
#pragma unroll
            for (int i = 0; i < 4; i++) {
                int r0 = m0 + wm * 64 + i * 16 + g;
                if (r0 < cnt) {
                    float2 v;
                    v.x = f2tf32f(fmaxf(acc[i][j][0] + bv0, 0.f));
                    v.y = f2tf32f(fmaxf(acc[i][j][1] + bv1, 0.f));
                    *reinterpret_cast<float2*>(&g_h[(size_t)(base + r0) * ND + col]) = v;
                }
                int r1 = r0 + 8;
                if (r1 < cnt) {
                    float2 v;
                    v.x = f2tf32f(fmaxf(acc[i][j][2] + bv0, 0.f));
                    v.y = f2tf32f(fmaxf(acc[i][j][3] + bv1, 0.f));
                    *reinterpret_cast<float2*>(&g_h[(size_t)(base + r1) * ND + col]) = v;
                }
            }
        }
    } else {
        int kv = kp ? __ldg(kp) : Kq;
        if (kv <= 0) kv = Kq;
        float inv_k = 1.0f / (float)kv;
#pragma unroll
        for (int j = 0; j < 4; j++) {
            int col = n0 + wn * 32 + j * 8 + 2 * c;
            float bv0 = __ldg(bias + (size_t)e * ND + col);
            float bv1 = __ldg(bias + (size_t)e * ND + col + 1);
#pragma unroll
            for (int i = 0; i < 4; i++) {
                int r0 = m0 + wm * 64 + i * 16 + g;
                if (r0 < cnt) {
                    float* op = out + (size_t)toks[r0 - m0] * ND + col;
                    atomicAdd(op,     (acc[i][j][0] + bv0) * inv_k);
                    atomicAdd(op + 1, (acc[i][j][1] + bv1) * inv_k);
                }
                int r1 = r0 + 8;
                if (r1 < cnt) {
                    float* op = out + (size_t)toks[r1 - m0] * ND + col;
                    atomicAdd(op,     (acc[i][j][2] + bv0) * inv_k);
                    atomicAdd(op + 1, (acc[i][j][3] + bv1) * inv_k);
                }
            }
        }
    }
}

// ---------------------------------------------------------------------
// launch
// ---------------------------------------------------------------------
extern "C" void kernel_launch(void* const* d_in, const int* in_sizes, int n_in,
                              void* d_out, int out_size) {
    const float* x      = (const float*)d_in[0];
    const float* W1     = (const float*)d_in[1];
    const float* b1     = (const float*)d_in[2];
    const float* W2     = (const float*)d_in[3];
    const float* b2     = (const float*)d_in[4];
    const int*   assign = (const int*)d_in[5];
    const int*   kp     = (n_in >= 7) ? (const int*)d_in[6] : nullptr;
    float* out = (float*)d_out;

    k_zero<<<1024, 256>>>(out, out_size);
    k_detect<<<16, 256>>>(assign);
    k_build<<<16, 256>>>(assign);

    // prepass: tf32-round x, W1, W2 (RNA) into device buffers
    float* xr;  cudaGetSymbolAddress((void**)&xr,  g_xr);
    float* w1r; cudaGetSymbolAddress((void**)&w1r, g_w1r);
    float* w2r; cudaGetSymbolAddress((void**)&w2r, g_w2r);
    k_round4<<<1024, 256>>>(xr,  x,  NTOK * Dq / 4);
    k_round4<<<4096, 256>>>(w1r, W1, Eq * Dq * Hq / 4);
    k_round4<<<4096, 256>>>(w2r, W2, Eq * Hq * Dq / 4);

    cudaFuncSetAttribute(k_gemm_tc<Dq, Hq, true>,
                         cudaFuncAttributeMaxDynamicSharedMemorySize, SMEM_TOTAL);
    cudaFuncSetAttribute(k_gemm_tc<Hq, Dq, false>,
                         cudaFuncAttributeMaxDynamicSharedMemorySize, SMEM_TOTAL);

    // GEMM1: [rows,1024] @ [1024,4096] -> relu -> g_h (tf32-rounded)
    dim3 g1(Hq / 128, NTOK / 128, Eq);
    k_gemm_tc<Dq, Hq, true><<<g1, 256, SMEM_TOTAL>>>(xr, w1r, b1, nullptr, nullptr);

    // GEMM2: [rows,4096] @ [4096,1024] -> scatter-add out
    dim3 g2(Dq / 128, NTOK / 128, Eq);
    k_gemm_tc<Hq, Dq, false><<<g2, 256, SMEM_TOTAL>>>(nullptr, w2r, b2, out, kp);
}

// round 7
// speedup vs baseline: 1.3490x; 1.0193x over previous
#include <cuda_runtime.h>
#include <cuda_bf16.h>
#include <cstdint>

// Problem constants (fixed for MoELayer_20761871908984)
#define Bq     4
#define Sq     1024
#define Dq     1024
#define Hq     4096
#define Eq     8
#define Kq     2
#define NTOK   (Bq * Sq)        // 4096 tokens
#define MAXROW (NTOK * Kq)      // 8192 max (token, expert) rows
#define MAXTIL 96               // >= sum ceil(cnt_e/128) (bound: 8192/128 + 7 = 71)

// -------- device-global scratch (no runtime allocation allowed) --------
__device__ int   g_counts[Eq];
__device__ int   g_lists[Eq][NTOK];
__device__ int   g_odd_nonzero;              // !=0 -> assign int32; ==0 -> int64
__device__ int   g_tile_e[MAXTIL];
__device__ int   g_tile_m[MAXTIL];
__device__ int   g_base[Eq];
__device__ int   g_ntiles;
__device__ float g_h[(size_t)MAXROW * Hq];   // hidden activations (tf32-rounded)
__device__ float g_xr[(size_t)NTOK * Dq];    // x, tf32-rounded

// ---------------------------------------------------------------------
__global__ void k_zero(float* __restrict__ out, int n) {
    int i = blockIdx.x * blockDim.x + threadIdx.x;
    int stride = gridDim.x * blockDim.x;
    float4 z = make_float4(0.f, 0.f, 0.f, 0.f);
    int n4 = n >> 2;
    for (int j = i; j < n4; j += stride)
        reinterpret_cast<float4*>(out)[j] = z;
    for (int j = (n4 << 2) + i; j < n; j += stride)
        out[j] = 0.f;
    if (i == 0) {
        g_odd_nonzero = 0;
#pragma unroll
        for (int e = 0; e < Eq; e++) g_counts[e] = 0;
    }
}

__global__ void k_detect(const int* __restrict__ a32) {
    int i = blockIdx.x * blockDim.x + threadIdx.x;   // [0, 4096)
    int idx = 2 * i + 1;
    if (idx < NTOK * Kq) {
        if (a32[idx] != 0) atomicOr(&g_odd_nonzero, 1);
    }
}

__global__ void k_build(const int* __restrict__ a32) {
    int t = blockIdx.x * blockDim.x + threadIdx.x;
    if (t >= NTOK) return;
    int is64 = (g_odd_nonzero == 0);
    unsigned mask = 0;
#pragma unroll
    for (int j = 0; j < Kq; j++) {
        int e;
        if (is64) e = a32[(t * Kq + j) * 2];
        else      e = a32[t * Kq + j];
        mask |= 1u << (e & (Eq - 1));
    }
    while (mask) {
        int e = __ffs(mask) - 1;
        mask &= mask - 1;
        int p = atomicAdd(&g_counts[e], 1);
        g_lists[e][p] = t;
    }
}

// Build the (expert, m-tile) work table + per-expert row bases.
__global__ void k_tiles() {
    if (threadIdx.x != 0 || blockIdx.x != 0) return;
    int base = 0, nt = 0;
#pragma unroll
    for (int e = 0; e < Eq; e++) {
        int cnt = g_counts[e];
        g_base[e] = base;
        for (int m0 = 0; m0 < cnt && nt < MAXTIL; m0 += 128) {
            g_tile_e[nt] = e;
            g_tile_m[nt] = m0;
            nt++;
        }
        base += cnt;
    }
    g_ntiles = nt;
}

// ---------------------------------------------------------------------
// tf32 helpers
// ---------------------------------------------------------------------
__device__ __forceinline__ unsigned f2tf32(float f) {
    unsigned r;
    asm volatile("cvt.rna.tf32.f32 %0, %1;\n" : "=r"(r) : "f"(f));
    return r;
}
__device__ __forceinline__ float f2tf32f(float f) {
    return __uint_as_float(f2tf32(f));
}

// Prepass (x only): dst = tf32_rna(src)
__global__ void k_round4(float* __restrict__ dst, const float* __restrict__ src, int n4) {
    int i = blockIdx.x * blockDim.x + threadIdx.x;
    int stride = gridDim.x * blockDim.x;
    for (; i < n4; i += stride) {
        float4 v = reinterpret_cast<const float4*>(src)[i];
        v.x = f2tf32f(v.x); v.y = f2tf32f(v.y);
        v.z = f2tf32f(v.z); v.w = f2tf32f(v.w);
        reinterpret_cast<float4*>(dst)[i] = v;
    }
}

__device__ __forceinline__ void mma_tf32(float& d0, float& d1, float& d2, float& d3,
                                         unsigned a0, unsigned a1, unsigned a2, unsigned a3,
                                         unsigned b0, unsigned b1) {
    asm volatile(
        "mma.sync.aligned.m16n8k8.row.col.f32.tf32.tf32.f32 "
        "{%0,%1,%2,%3},{%4,%5,%6,%7},{%8,%9},{%0,%1,%2,%3};\n"
        : "+f"(d0), "+f"(d1), "+f"(d2), "+f"(d3)
        : "r"(a0), "r"(a1), "r"(a2), "r"(a3), "r"(b0), "r"(b1));
}

__device__ __forceinline__ void ldsm_x4(unsigned& r0, unsigned& r1, unsigned& r2, unsigned& r3,
                                        uint32_t addr) {
    asm volatile("ldmatrix.sync.aligned.m8n8.x4.shared.b16 {%0,%1,%2,%3}, [%4];\n"
                 : "=r"(r0), "=r"(r1), "=r"(r2), "=r"(r3) : "r"(addr));
}

__device__ __forceinline__ void cp_async16(uint32_t smem_addr, const void* gptr) {
    asm volatile("cp.async.cg.shared.global [%0], [%1], 16;\n"
                 :: "r"(smem_addr), "l"(gptr));
}
__device__ __forceinline__ void cp_commit() { asm volatile("cp.async.commit_group;\n"); }
__device__ __forceinline__ void cp_wait1()  { asm volatile("cp.async.wait_group 1;\n"); }
__device__ __forceinline__ void cp_wait0()  { asm volatile("cp.async.wait_group 0;\n"); }

// ---------------------------------------------------------------------
// Smem geometry: BK=32 per stage, 3 stages.
// A: [128][ASTR] floats, ASTR=36 -> conflict-free LDSM phases.
// B: [32][BSTR]  floats, BSTR=136 -> conflict-free scalar frags + STS.128.
// ---------------------------------------------------------------------
#define ASTR 36
#define BSTR 136
#define NSTG 3
#define A_TILE_FLT (128 * ASTR)
#define B_TILE_FLT (32 * BSTR)
#define OFF_TOKS   0
#define OFF_A      512
#define OFF_B      (OFF_A + NSTG * A_TILE_FLT * 4)
#define SMEM_TOTAL (OFF_B + NSTG * B_TILE_FLT * 4)

// ---------------------------------------------------------------------
// tf32 grouped GEMM (mma.sync.m16n8k8).
// CTA tile 128x128, BK=32/stage, 256 threads, 8 warps 64x32.
// A: cp.async (pre-rounded source). B: raw W via LDG.128 (1 stage ahead)
//    -> cvt.rna.tf32 -> STS.128 (rounding fused into staging).
// ---------------------------------------------------------------------
template<int KD, int ND, bool G1>
__global__ void __launch_bounds__(256, 2)
k_gemm_tc(const float* __restrict__ Ain,      // G1: g_xr ; G2: g_h
          const float* __restrict__ W,        // RAW fp32 [E][KD][ND]
          const float* __restrict__ bias,
          float* __restrict__ out,
          const int* __restrict__ kp)
{
    constexpr int NK = KD / 32;
    const int ti = blockIdx.y;
    if (ti >= g_ntiles) return;
    const int e    = g_tile_e[ti];
    const int m0   = g_tile_m[ti];
    const int cnt  = g_counts[e];
    const int base = g_base[e];
    const int n0   = blockIdx.x * 128;

    extern __shared__ __align__(16) char smem[];
    int*   toks = reinterpret_cast<int*>(smem + OFF_TOKS);
    float* As   = reinterpret_cast<float*>(smem + OFF_A);
    float* Bs   = reinterpret_cast<float*>(smem + OFF_B);

    const int tid  = threadIdx.x;
    const int lane = tid & 31;
    const int wid  = tid >> 5;
    const int wm   = wid >> 2;     // 0..1
    const int wn   = wid & 3;      // 0..3
    const int g    = lane >> 2;    // 0..7
    const int c    = lane & 3;     // 0..3

    if (tid < 128) {
        int row = m0 + tid;
        toks[tid] = (row < cnt) ? g_lists[e][row] : 0;
    }
    __syncthreads();

    // ---- A staging (cp.async): 4 chunks/thread; m = tid>>3 + 32i, quad aq ----
    const int aq = tid & 7;
    const float* aSrc[4];
    uint32_t aDst[4];
#pragma unroll
    for (int i = 0; i < 4; i++) {
        int m = (tid >> 3) + 32 * i;
        int row = m0 + m;
        if (G1) aSrc[i] = Ain + (size_t)toks[m] * KD + 4 * aq;
        else    aSrc[i] = g_h + (size_t)((row < cnt) ? base + row : base) * KD + 4 * aq;
        aDst[i] = (uint32_t)((m * ASTR + 4 * aq) * 4);
    }
    const uint32_t sbA = (uint32_t)__cvta_generic_to_shared(As);

    auto ldgA = [&](int kt, int buf) {
        const uint32_t dA = sbA + buf * A_TILE_FLT * 4;
        const int k0 = kt * 32;
#pragma unroll
        for (int i = 0; i < 4; i++)
            cp_async16(dA + aDst[i], aSrc[i] + k0);
        cp_commit();
    };

    // ---- B staging (LDG -> cvt.rna -> STS): k = wid + 8i, n quad = lane ----
    const float* bSrc = W + (size_t)e * KD * ND + (size_t)wid * ND + n0 + 4 * lane;
    float4 rb[4];
    auto ldgB = [&](int kt) {
#pragma unroll
        for (int i = 0; i < 4; i++)
            rb[i] = __ldg(reinterpret_cast<const float4*>(
                bSrc + ((size_t)kt * 32 + 8 * i) * ND));
    };
    auto stsB = [&](int buf) {
        float* Bb = Bs + buf * B_TILE_FLT;
#pragma unroll
        for (int i = 0; i < 4; i++) {
            float4 v;
            v.x = f2tf32f(rb[i].x); v.y = f2tf32f(rb[i].y);
            v.z = f2tf32f(rb[i].z); v.w = f2tf32f(rb[i].w);
            *reinterpret_cast<float4*>(&Bb[(wid + 8 * i) * BSTR + 4 * lane]) = v;
        }
    };

    float acc[4][4][4];
#pragma unroll
    for (int i = 0; i < 4; i++)
#pragma unroll
        for (int j = 0; j < 4; j++)
#pragma unroll
            for (int r = 0; r < 4; r++) acc[i][j][r] = 0.f;

    // ---- prologue ----
    ldgB(0); stsB(0);
    ldgB(1); stsB(1);
    ldgA(0, 0);
    ldgA(1, 1);
    if (NK > 2) ldgB(2);

    // ldmatrix lane addressing
    const int lrow = wm * 64 + (lane & 15);
    const int lcol = (lane >> 4) * 4;

    for (int kt = 0; kt < NK; kt++) {
        const int buf = kt % NSTG;
        if (kt + 1 < NK) cp_wait1(); else cp_wait0();
        __syncthreads();
        if (kt + 2 < NK) {
            stsB((kt + 2) % NSTG);          // rb holds stage kt+2
            ldgA(kt + 2, (kt + 2) % NSTG);
            if (kt + 3 < NK) ldgB(kt + 3);  // refill rb (after stsB consumed it)
        }

        const float* Ab = As + buf * A_TILE_FLT;
        const float* Bb = Bs + buf * B_TILE_FLT;

#pragma unroll
        for (int h = 0; h < 2; h++) {        // two 16-k halves of BK=32
            const int kh = h * 16;
#pragma unroll
            for (int k8 = 0; k8 < 2; k8++) {
                const int kb = kh + k8 * 8;
                unsigned bf[4][2];
#pragma unroll
                for (int j = 0; j < 4; j++) {
                    int nn = wn * 32 + j * 8 + g;
                    bf[j][0] = __float_as_uint(Bb[(kb + c) * BSTR + nn]);
                    bf[j][1] = __float_as_uint(Bb[(kb + c + 4) * BSTR + nn]);
                }
#pragma unroll
                for (int i = 0; i < 4; i++) {
                    uint32_t abase = (uint32_t)__cvta_generic_to_shared(
                        Ab + (lrow + i * 16) * ASTR + kb + lcol - (k8 ? 4 : 0) + (k8 ? 0 : 0));
                    // A fragment for this k8: k-range [kb, kb+8)
                    unsigned a0, a1, a2, a3;
                    ldsm_x4(a0, a1, a2, a3,
                            (uint32_t)__cvta_generic_to_shared(
                                Ab + (lrow + i * 16) * ASTR + kb + lcol));
#pragma unroll
                    for (int j = 0; j < 4; j++)
                        mma_tf32(acc[i][j][0], acc[i][j][1], acc[i][j][2], acc[i][j][3],
                                 a0, a1, a2, a3, bf[j][0], bf[j][1]);
                }
            }
        }
    }

    // ---- epilogue ----
    if (G1) {
#pragma unroll
        for (int j = 0; j < 4; j++) {
            int col = n0 + wn * 32 + j * 8 + 2 * c;
            float bv0 = __ldg(bias + (size_t)e * ND + col);
            float bv1 = __ldg(bias + (size_t)e * ND + col + 1);
#pragma unroll
            for (int i = 0; i < 4; i++) {
                int r0 = m0 + wm * 64 + i * 16 + g;
                if (r0 < cnt) {
                    float2 v;
                    v.x = f2tf32f(fmaxf(acc[i][j][0] + bv0, 0.f));
                    v.y = f2tf32f(fmaxf(acc[i][j][1] + bv1, 0.f));
                    *reinterpret_cast<float2*>(&g_h[(size_t)(base + r0) * ND + col]) = v;
                }
                int r1 = r0 + 8;
                if (r1 < cnt) {
                    float2 v;
                    v.x = f2tf32f(fmaxf(acc[i][j][2] + bv0, 0.f));
                    v.y = f2tf32f(fmaxf(acc[i][j][3] + bv1, 0.f));
                    *reinterpret_cast<float2*>(&g_h[(size_t)(base + r1) * ND + col]) = v;
                }
            }
        }
    } else {
        int kv = kp ? __ldg(kp) : Kq;
        if (kv <= 0) kv = Kq;
        float inv_k = 1.0f / (float)kv;
#pragma unroll
        for (int j = 0; j < 4; j++) {
            int col = n0 + wn * 32 + j * 8 + 2 * c;
            float bv0 = __ldg(bias + (size_t)e * ND + col);
            float bv1 = __ldg(bias + (size_t)e * ND + col + 1);
#pragma unroll
            for (int i = 0; i < 4; i++) {
                int r0 = m0 + wm * 64 + i * 16 + g;
                if (r0 < cnt) {
                    float* op = out + (size_t)toks[r0 - m0] * ND + col;
                    atomicAdd(op,     (acc[i][j][0] + bv0) * inv_k);
                    atomicAdd(op + 1, (acc[i][j][1] + bv1) * inv_k);
                }
                int r1 = r0 + 8;
                if (r1 < cnt) {
                    float* op = out + (size_t)toks[r1 - m0] * ND + col;
                    atomicAdd(op,     (acc[i][j][2] + bv0) * inv_k);
                    atomicAdd(op + 1, (acc[i][j][3] + bv1) * inv_k);
                }
            }
        }
    }
}

// ---------------------------------------------------------------------
// launch
// ---------------------------------------------------------------------
extern "C" void kernel_launch(void* const* d_in, const int* in_sizes, int n_in,
                              void* d_out, int out_size) {
    const float* x      = (const float*)d_in[0];
    const float* W1     = (const float*)d_in[1];
    const float* b1     = (const float*)d_in[2];
    const float* W2     = (const float*)d_in[3];
    const float* b2     = (const float*)d_in[4];
    const int*   assign = (const int*)d_in[5];
    const int*   kp     = (n_in >= 7) ? (const int*)d_in[6] : nullptr;
    float* out = (float*)d_out;

    k_zero<<<1024, 256>>>(out, out_size);
    k_detect<<<16, 256>>>(assign);
    k_build<<<16, 256>>>(assign);
    k_tiles<<<1, 32>>>();

    // x -> tf32 (RNA); weights are rounded inside GEMM staging
    float* xr; cudaGetSymbolAddress((void**)&xr, g_xr);
    k_round4<<<1024, 256>>>(xr, x, NTOK * Dq / 4);

    cudaFuncSetAttribute(k_gemm_tc<Dq, Hq, true>,
                         cudaFuncAttributeMaxDynamicSharedMemorySize, SMEM_TOTAL);
    cudaFuncSetAttribute(k_gemm_tc<Hq, Dq, false>,
                         cudaFuncAttributeMaxDynamicSharedMemorySize, SMEM_TOTAL);

    // GEMM1: [rows,1024] @ [1024,4096] -> relu -> g_h (tf32-rounded)
    dim3 g1(Hq / 128, MAXTIL - 24, 1);     // y = 72 work items (tile table)
    k_gemm_tc<Dq, Hq, true><<<g1, 256, SMEM_TOTAL>>>(xr, W1, b1, nullptr, nullptr);

    // GEMM2: [rows,4096] @ [4096,1024] -> scatter-add out
    dim3 g2(Dq / 128, MAXTIL - 24, 1);
    k_gemm_tc<Hq, Dq, false><<<g2, 256, SMEM_TOTAL>>>(nullptr, W2, b2, out, kp);
}

// round 8
// speedup vs baseline: 1.3621x; 1.0097x over previous
#include <cuda_runtime.h>
#include <cuda_bf16.h>
#include <cstdint>

// Problem constants (fixed for MoELayer_20761871908984)
#define Bq     4
#define Sq     1024
#define Dq     1024
#define Hq     4096
#define Eq     8
#define Kq     2
#define NTOK   (Bq * Sq)        // 4096 tokens
#define MAXROW (NTOK * Kq)      // 8192 max (token, expert) rows
#define MAXTIL 96

// -------- device-global scratch (no runtime allocation allowed) --------
__device__ int   g_counts[Eq];
__device__ int   g_lists[Eq][NTOK];
__device__ int   g_odd_nonzero;              // !=0 -> assign int32; ==0 -> int64
__device__ int   g_tile_e[MAXTIL];
__device__ int   g_tile_m[MAXTIL];
__device__ int   g_base[Eq];
__device__ int   g_ntiles;
__device__ float g_h[(size_t)MAXROW * Hq];   // hidden activations (tf32-rounded)
__device__ float g_xr[(size_t)NTOK * Dq];    // x, tf32-rounded

// ---------------------------------------------------------------------
__global__ void k_zero(float* __restrict__ out, int n) {
    int i = blockIdx.x * blockDim.x + threadIdx.x;
    int stride = gridDim.x * blockDim.x;
    float4 z = make_float4(0.f, 0.f, 0.f, 0.f);
    int n4 = n >> 2;
    for (int j = i; j < n4; j += stride)
        reinterpret_cast<float4*>(out)[j] = z;
    for (int j = (n4 << 2) + i; j < n; j += stride)
        out[j] = 0.f;
    if (i == 0) {
        g_odd_nonzero = 0;
#pragma unroll
        for (int e = 0; e < Eq; e++) g_counts[e] = 0;
    }
}

__global__ void k_detect(const int* __restrict__ a32) {
    int i = blockIdx.x * blockDim.x + threadIdx.x;   // [0, 4096)
    int idx = 2 * i + 1;
    if (idx < NTOK * Kq) {
        if (a32[idx] != 0) atomicOr(&g_odd_nonzero, 1);
    }
}

__global__ void k_build(const int* __restrict__ a32) {
    int t = blockIdx.x * blockDim.x + threadIdx.x;
    if (t >= NTOK) return;
    int is64 = (g_odd_nonzero == 0);
    unsigned mask = 0;
#pragma unroll
    for (int j = 0; j < Kq; j++) {
        int e;
        if (is64) e = a32[(t * Kq + j) * 2];
        else      e = a32[t * Kq + j];
        mask |= 1u << (e & (Eq - 1));
    }
    while (mask) {
        int e = __ffs(mask) - 1;
        mask &= mask - 1;
        int p = atomicAdd(&g_counts[e], 1);
        g_lists[e][p] = t;
    }
}

// Build the (expert, m-tile) work table + per-expert row bases.
__global__ void k_tiles() {
    if (threadIdx.x != 0 || blockIdx.x != 0) return;
    int base = 0, nt = 0;
#pragma unroll
    for (int e = 0; e < Eq; e++) {
        int cnt = g_counts[e];
        g_base[e] = base;
        for (int m0 = 0; m0 < cnt && nt < MAXTIL; m0 += 128) {
            g_tile_e[nt] = e;
            g_tile_m[nt] = m0;
            nt++;
        }
        base += cnt;
    }
    g_ntiles = nt;
}

// ---------------------------------------------------------------------
// tf32 helpers
// ---------------------------------------------------------------------
__device__ __forceinline__ unsigned f2tf32(float f) {
    unsigned r;
    asm volatile("cvt.rna.tf32.f32 %0, %1;\n" : "=r"(r) : "f"(f));
    return r;
}
__device__ __forceinline__ float f2tf32f(float f) {
    return __uint_as_float(f2tf32(f));
}

// Prepass (x only): dst = tf32_rna(src)
__global__ void k_round4(float* __restrict__ dst, const float* __restrict__ src, int n4) {
    int i = blockIdx.x * blockDim.x + threadIdx.x;
    int stride = gridDim.x * blockDim.x;
    for (; i < n4; i += stride) {
        float4 v = reinterpret_cast<const float4*>(src)[i];
        v.x = f2tf32f(v.x); v.y = f2tf32f(v.y);
        v.z = f2tf32f(v.z); v.w = f2tf32f(v.w);
        reinterpret_cast<float4*>(dst)[i] = v;
    }
}

__device__ __forceinline__ void mma_tf32(float& d0, float& d1, float& d2, float& d3,
                                         unsigned a0, unsigned a1, unsigned a2, unsigned a3,
                                         unsigned b0, unsigned b1) {
    asm volatile(
        "mma.sync.aligned.m16n8k8.row.col.f32.tf32.tf32.f32 "
        "{%0,%1,%2,%3},{%4,%5,%6,%7},{%8,%9},{%0,%1,%2,%3};\n"
        : "+f"(d0), "+f"(d1), "+f"(d2), "+f"(d3)
        : "r"(a0), "r"(a1), "r"(a2), "r"(a3), "r"(b0), "r"(b1));
}

__device__ __forceinline__ void ldsm_x4(unsigned& r0, unsigned& r1, unsigned& r2, unsigned& r3,
                                        uint32_t addr) {
    asm volatile("ldmatrix.sync.aligned.m8n8.x4.shared.b16 {%0,%1,%2,%3}, [%4];\n"
                 : "=r"(r0), "=r"(r1), "=r"(r2), "=r"(r3) : "r"(addr));
}

__device__ __forceinline__ void cp_async16(uint32_t smem_addr, const void* gptr) {
    asm volatile("cp.async.cg.shared.global [%0], [%1], 16;\n"
                 :: "r"(smem_addr), "l"(gptr));
}
__device__ __forceinline__ void cp_commit() { asm volatile("cp.async.commit_group;\n"); }
__device__ __forceinline__ void cp_wait1()  { asm volatile("cp.async.wait_group 1;\n"); }
__device__ __forceinline__ void cp_wait0()  { asm volatile("cp.async.wait_group 0;\n"); }

// ---------------------------------------------------------------------
// Smem geometry: BK=32 per stage, 3 stages.
// A: [128][ASTR] floats, ASTR=36 -> conflict-free LDSM phases.
// B: [32][BSTR]  floats, BSTR=136 -> conflict-free scalar frags.
// ---------------------------------------------------------------------
#define ASTR 36
#define BSTR 136
#define NSTG 3
#define A_TILE_FLT (128 * ASTR)
#define B_TILE_FLT (32 * BSTR)
#define OFF_TOKS   0
#define OFF_A      512
#define OFF_B      (OFF_A + NSTG * A_TILE_FLT * 4)
#define SMEM_TOTAL (OFF_B + NSTG * B_TILE_FLT * 4)

// ---------------------------------------------------------------------
// tf32 grouped GEMM (mma.sync.m16n8k8).
// CTA tile 128x128, BK=32/stage, 256 threads, 8 warps 64x32.
// Both operands staged by cp.async (A pre-rounded source; B raw W,
// cvt.rna applied at fragment load — identical rounding points).
// Fragment double-buffering: A one i ahead, B one k8 ahead.
// ---------------------------------------------------------------------
template<int KD, int ND, bool G1>
__global__ void __launch_bounds__(256, 2)
k_gemm_tc(const float* __restrict__ Ain,      // G1: g_xr ; G2: g_h
          const float* __restrict__ W,        // RAW fp32 [E][KD][ND]
          const float* __restrict__ bias,
          float* __restrict__ out,
          const int* __restrict__ kp)
{
    constexpr int NK = KD / 32;
    const int ti = blockIdx.y;
    if (ti >= g_ntiles) return;
    const int e    = g_tile_e[ti];
    const int m0   = g_tile_m[ti];
    const int cnt  = g_counts[e];
    const int base = g_base[e];
    const int n0   = blockIdx.x * 128;

    extern __shared__ __align__(16) char smem[];
    int*   toks = reinterpret_cast<int*>(smem + OFF_TOKS);
    float* As   = reinterpret_cast<float*>(smem + OFF_A);
    float* Bs   = reinterpret_cast<float*>(smem + OFF_B);

    const int tid  = threadIdx.x;
    const int lane = tid & 31;
    const int wid  = tid >> 5;
    const int wm   = wid >> 2;     // 0..1
    const int wn   = wid & 3;      // 0..3
    const int g    = lane >> 2;    // 0..7
    const int c    = lane & 3;     // 0..3

    if (tid < 128) {
        int row = m0 + tid;
        toks[tid] = (row < cnt) ? g_lists[e][row] : 0;
    }
    __syncthreads();

    // ---- A staging (cp.async): 4 chunks/thread ----
    const int aq = tid & 7;
    const float* aSrc[4];
    uint32_t aDst[4];
#pragma unroll
    for (int i = 0; i < 4; i++) {
        int m = (tid >> 3) + 32 * i;
        int row = m0 + m;
        if (G1) aSrc[i] = Ain + (size_t)toks[m] * KD + 4 * aq;
        else    aSrc[i] = g_h + (size_t)((row < cnt) ? base + row : base) * KD + 4 * aq;
        aDst[i] = (uint32_t)((m * ASTR + 4 * aq) * 4);
    }
    // ---- B staging (cp.async, raw W): k = tid>>5 + 8i, n quad = tid&31 ----
    const int bnq = tid & 31;
    const int bk0 = tid >> 5;
    const float* Wp = W + (size_t)e * KD * ND;
    const uint32_t sbA = (uint32_t)__cvta_generic_to_shared(As);
    const uint32_t sbB = (uint32_t)__cvta_generic_to_shared(Bs);

    auto load_stage = [&](int kt, int buf) {
        const int k0 = kt * 32;
        const uint32_t dA = sbA + buf * A_TILE_FLT * 4;
        const uint32_t dB = sbB + buf * B_TILE_FLT * 4;
#pragma unroll
        for (int i = 0; i < 4; i++)
            cp_async16(dA + aDst[i], aSrc[i] + k0);
#pragma unroll
        for (int i = 0; i < 4; i++) {
            int k = bk0 + 8 * i;
            cp_async16(dB + (uint32_t)((k * BSTR + 4 * bnq) * 4),
                       Wp + (size_t)(k0 + k) * ND + n0 + 4 * bnq);
        }
        cp_commit();
    };

    float acc[4][4][4];
#pragma unroll
    for (int i = 0; i < 4; i++)
#pragma unroll
        for (int j = 0; j < 4; j++)
#pragma unroll
            for (int r = 0; r < 4; r++) acc[i][j][r] = 0.f;

    load_stage(0, 0);
    load_stage(1, 1);

    // ldmatrix lane addressing
    const int lrow = wm * 64 + (lane & 15);
    const int lcol = (lane >> 4) * 4;
    const int bnn0 = wn * 32 + g;

    for (int kt = 0; kt < NK; kt++) {
        const int buf = kt % NSTG;
        if (kt + 1 < NK) cp_wait1(); else cp_wait0();
        __syncthreads();
        if (kt + 2 < NK) load_stage(kt + 2, (kt + 2) % NSTG);

        const float* Ab = As + buf * A_TILE_FLT;
        const float* Bb = Bs + buf * B_TILE_FLT;

        // fragment double buffers
        unsigned bf0[4][2], bf1[4][2];
        unsigned ac[4], an[4];

        // prefetch k8=0 B frags (cvt.rna at load) and i=0 A frag
#pragma unroll
        for (int j = 0; j < 4; j++) {
            int nn = bnn0 + j * 8;
            bf0[j][0] = f2tf32(Bb[(c) * BSTR + nn]);
            bf0[j][1] = f2tf32(Bb[(c + 4) * BSTR + nn]);
        }
        ldsm_x4(ac[0], ac[1], ac[2], ac[3],
                (uint32_t)__cvta_generic_to_shared(Ab + lrow * ASTR + lcol));

#pragma unroll
        for (int k8 = 0; k8 < 4; k8++) {
            const int kb = k8 * 8;
            unsigned (*bcur)[2] = (k8 & 1) ? bf1 : bf0;
            unsigned (*bnxt)[2] = (k8 & 1) ? bf0 : bf1;
#pragma unroll
            for (int i = 0; i < 4; i++) {
                // prefetch next fragments
                if (i < 3) {
                    ldsm_x4(an[0], an[1], an[2], an[3],
                            (uint32_t)__cvta_generic_to_shared(
                                Ab + (lrow + (i + 1) * 16) * ASTR + kb + lcol));
                } else if (k8 < 3) {
#pragma unroll
                    for (int j = 0; j < 4; j++) {
                        int nn = bnn0 + j * 8;
                        bnxt[j][0] = f2tf32(Bb[(kb + 8 + c) * BSTR + nn]);
                        bnxt[j][1] = f2tf32(Bb[(kb + 8 + c + 4) * BSTR + nn]);
                    }
                    ldsm_x4(an[0], an[1], an[2], an[3],
                            (uint32_t)__cvta_generic_to_shared(
                                Ab + lrow * ASTR + kb + 8 + lcol));
                }
#pragma unroll
                for (int j = 0; j < 4; j++)
                    mma_tf32(acc[i][j][0], acc[i][j][1], acc[i][j][2], acc[i][j][3],
                             ac[0], ac[1], ac[2], ac[3],
                             bcur[j][0], bcur[j][1]);
#pragma unroll
                for (int r = 0; r < 4; r++) ac[r] = an[r];
            }
        }
    }

    // ---- epilogue ----
    if (G1) {
#pragma unroll
        for (int j = 0; j < 4; j++) {
            int col = n0 + wn * 32 + j * 8 + 2 * c;
            float bv0 = __ldg(bias + (size_t)e * ND + col);
            float bv1 = __ldg(bias + (size_t)e * ND + col + 1);
#pragma unroll
            for (int i = 0; i < 4; i++) {
                int r0 = m0 + wm * 64 + i * 16 + g;
                if (r0 < cnt) {
                    float2 v;
                    v.x = f2tf32f(fmaxf(acc[i][j][0] + bv0, 0.f));
                    v.y = f2tf32f(fmaxf(acc[i][j][1] + bv1, 0.f));
                    *reinterpret_cast<float2*>(&g_h[(size_t)(base + r0) * ND + col]) = v;
                }
                int r1 = r0 + 8;
                if (r1 < cnt) {
                    float2 v;
                    v.x = f2tf32f(fmaxf(acc[i][j][2] + bv0, 0.f));
                    v.y = f2tf32f(fmaxf(acc[i][j][3] + bv1, 0.f));
                    *reinterpret_cast<float2*>(&g_h[(size_t)(base + r1) * ND + col]) = v;
                }
            }
        }
    } else {
        int kv = kp ? __ldg(kp) : Kq;
        if (kv <= 0) kv = Kq;
        float inv_k = 1.0f / (float)kv;
#pragma unroll
        for (int j = 0; j < 4; j++) {
            int col = n0 + wn * 32 + j * 8 + 2 * c;
            float bv0 = __ldg(bias + (size_t)e * ND + col);
            float bv1 = __ldg(bias + (size_t)e * ND + col + 1);
#pragma unroll
            for (int i = 0; i < 4; i++) {
                int r0 = m0 + wm * 64 + i * 16 + g;
                if (r0 < cnt) {
                    float* op = out + (size_t)toks[r0 - m0] * ND + col;
                    atomicAdd(op,     (acc[i][j][0] + bv0) * inv_k);
                    atomicAdd(op + 1, (acc[i][j][1] + bv1) * inv_k);
                }
                int r1 = r0 + 8;
                if (r1 < cnt) {
                    float* op = out + (size_t)toks[r1 - m0] * ND + col;
                    atomicAdd(op,     (acc[i][j][2] + bv0) * inv_k);
                    atomicAdd(op + 1, (acc[i][j][3] + bv1) * inv_k);
                }
            }
        }
    }
}

// ---------------------------------------------------------------------
// launch
// ---------------------------------------------------------------------
extern "C" void kernel_launch(void* const* d_in, const int* in_sizes, int n_in,
                              void* d_out, int out_size) {
    const float* x      = (const float*)d_in[0];
    const float* W1     = (const float*)d_in[1];
    const float* b1     = (const float*)d_in[2];
    const float* W2     = (const float*)d_in[3];
    const float* b2     = (const float*)d_in[4];
    const int*   assign = (const int*)d_in[5];
    const int*   kp     = (n_in >= 7) ? (const int*)d_in[6] : nullptr;
    float* out = (float*)d_out;

    k_zero<<<1024, 256>>>(out, out_size);
    k_detect<<<16, 256>>>(assign);
    k_build<<<16, 256>>>(assign);
    k_tiles<<<1, 32>>>();

    // x -> tf32 (RNA); weights rounded at fragment load inside GEMMs
    float* xr; cudaGetSymbolAddress((void**)&xr, g_xr);
    k_round4<<<1024, 256>>>(xr, x, NTOK * Dq / 4);

    cudaFuncSetAttribute(k_gemm_tc<Dq, Hq, true>,
                         cudaFuncAttributeMaxDynamicSharedMemorySize, SMEM_TOTAL);
    cudaFuncSetAttribute(k_gemm_tc<Hq, Dq, false>,
                         cudaFuncAttributeMaxDynamicSharedMemorySize, SMEM_TOTAL);

    // GEMM1: [rows,1024] @ [1024,4096] -> relu -> g_h (tf32-rounded)
    dim3 g1(Hq / 128, 72, 1);
    k_gemm_tc<Dq, Hq, true><<<g1, 256, SMEM_TOTAL>>>(xr, W1, b1, nullptr, nullptr);

    // GEMM2: [rows,4096] @ [4096,1024] -> scatter-add out
    dim3 g2(Dq / 128, 72, 1);
    k_gemm_tc<Hq, Dq, false><<<g2, 256, SMEM_TOTAL>>>(nullptr, W2, b2, out, kp);
}